// round 4
// baseline (speedup 1.0000x reference)
#include <cuda_runtime.h>
#include <math.h>

#define NNODE 6144
#define KFEAT 512
#define NH 256
#define NC 8
#define AD 128
#define NN4 (NNODE/4)

// ---------------- device scratch (no allocation allowed) ----------------
__device__ float g_adj[(size_t)NNODE * NNODE];   // combined adjacency
__device__ float g_S  [(size_t)NNODE * NNODE];   // masked logits / attention
__device__ float g_H0 [NNODE * NH];
__device__ float g_x  [NNODE * NH];
__device__ float g_Q  [NNODE * NH];
__device__ float g_K  [NNODE * NH];
__device__ float g_V  [NNODE * NH];
__device__ float g_Xt [NNODE * NH];
__device__ float g_MT [3][3][NNODE];             // folded Wa_k @ Wagg_k, transposed
__device__ float g_b4 [3];
__device__ float g_nzT[3][NNODE];                // nz transposed for coalesced combine
__device__ float g_nz_scratch[NNODE * 3];
__device__ float g_Y2T[NC][NNODE];               // (X_tilde @ W2) transposed

// ---------------- fold Wa_k @ Wagg_k -> M_k [N,3], and bias b4 ----------------
__global__ void k_precompute_M(const float* __restrict__ Wa1, const float* __restrict__ Wa2,
                               const float* __restrict__ Wa3, const float* __restrict__ Wagg,
                               const float* __restrict__ ba1, const float* __restrict__ ba2,
                               const float* __restrict__ ba3, const float* __restrict__ bagg)
{
    int t = blockIdx.x * blockDim.x + threadIdx.x;
    if (t < 3 * NNODE) {
        int k = t / NNODE, j = t % NNODE;
        const float* Wa = (k == 0) ? Wa1 : ((k == 1) ? Wa2 : Wa3);
        float a0 = 0.f, a1 = 0.f, a2 = 0.f;
        for (int a = 0; a < AD; a++) {
            float w = Wa[j * AD + a];
            const float* wg = Wagg + (k * AD + a) * 3;
            a0 = fmaf(w, wg[0], a0);
            a1 = fmaf(w, wg[1], a1);
            a2 = fmaf(w, wg[2], a2);
        }
        g_MT[k][0][j] = a0; g_MT[k][1][j] = a1; g_MT[k][2][j] = a2;
    }
    if (blockIdx.x == 0 && threadIdx.x < 3) {
        int c = threadIdx.x;
        float b = bagg[c];
        for (int k = 0; k < 3; k++) {
            const float* ba = (k == 0) ? ba1 : ((k == 1) ? ba2 : ba3);
            for (int a = 0; a < AD; a++) b = fmaf(ba[a], Wagg[(k * AD + a) * 3 + c], b);
        }
        g_b4[c] = b;
    }
}

// ---------------- pass A: z4 = sum_k adj_k @ M_k + b4 ; nz = softmax(z4) ----------------
__global__ __launch_bounds__(256)
void k_z4(const float* __restrict__ A0, const float* __restrict__ A1,
          const float* __restrict__ A2, float* __restrict__ nz_out)
{
    const int R = 8;
    int i0 = blockIdx.x * R;
    int tid = threadIdx.x;
    float acc[R][3];
#pragma unroll
    for (int r = 0; r < R; r++) { acc[r][0] = 0.f; acc[r][1] = 0.f; acc[r][2] = 0.f; }

    for (int jv = tid; jv < NN4; jv += 256) {
        int j = jv * 4;
        float4 m[3][3];
#pragma unroll
        for (int k = 0; k < 3; k++)
#pragma unroll
            for (int c = 0; c < 3; c++)
                m[k][c] = *(const float4*)&g_MT[k][c][j];
#pragma unroll
        for (int r = 0; r < R; r++) {
            size_t base = (size_t)(i0 + r) * NNODE + j;
            float4 a0 = *(const float4*)&A0[base];
            float4 a1 = *(const float4*)&A1[base];
            float4 a2 = *(const float4*)&A2[base];
#pragma unroll
            for (int c = 0; c < 3; c++) {
                float s = acc[r][c];
                s = fmaf(a0.x, m[0][c].x, s); s = fmaf(a0.y, m[0][c].y, s);
                s = fmaf(a0.z, m[0][c].z, s); s = fmaf(a0.w, m[0][c].w, s);
                s = fmaf(a1.x, m[1][c].x, s); s = fmaf(a1.y, m[1][c].y, s);
                s = fmaf(a1.z, m[1][c].z, s); s = fmaf(a1.w, m[1][c].w, s);
                s = fmaf(a2.x, m[2][c].x, s); s = fmaf(a2.y, m[2][c].y, s);
                s = fmaf(a2.z, m[2][c].z, s); s = fmaf(a2.w, m[2][c].w, s);
                acc[r][c] = s;
            }
        }
    }
    // warp reduce
#pragma unroll
    for (int off = 16; off; off >>= 1)
#pragma unroll
        for (int r = 0; r < R; r++)
#pragma unroll
            for (int c = 0; c < 3; c++)
                acc[r][c] += __shfl_down_sync(0xffffffffu, acc[r][c], off);

    __shared__ float red[8][24];
    __shared__ float z[8][3];
    int warp = tid >> 5, lane = tid & 31;
    if (lane == 0)
        for (int r = 0; r < R; r++)
            for (int c = 0; c < 3; c++)
                red[warp][r * 3 + c] = acc[r][c];
    __syncthreads();
    if (tid < 24) {
        float s = 0.f;
        for (int w = 0; w < 8; w++) s += red[w][tid];
        z[tid / 3][tid % 3] = s + g_b4[tid % 3];
    }
    __syncthreads();
    if (tid < 8) {
        int r = tid;
        float a = z[r][0], b = z[r][1], c = z[r][2];
        float mx = fmaxf(a, fmaxf(b, c));
        float e0 = expf(a - mx), e1 = expf(b - mx), e2 = expf(c - mx);
        float inv = 1.f / (e0 + e1 + e2);
        e0 *= inv; e1 *= inv; e2 *= inv;
        int i = i0 + r;
        nz_out[i * 3 + 0] = e0; nz_out[i * 3 + 1] = e1; nz_out[i * 3 + 2] = e2;
        g_nzT[0][i] = e0; g_nzT[1][i] = e1; g_nzT[2][i] = e2;
    }
}

// ---------------- pass B: adj[i,j] = sum_k nz[j,k] * adj_k[i,j]  (column scaling) ----------------
__global__ __launch_bounds__(256)
void k_combine(const float* __restrict__ A0, const float* __restrict__ A1,
               const float* __restrict__ A2)
{
    size_t total4 = (size_t)NNODE * NNODE / 4;
    size_t stride = (size_t)gridDim.x * blockDim.x;
    for (size_t idx = (size_t)blockIdx.x * blockDim.x + threadIdx.x; idx < total4; idx += stride) {
        size_t f = idx * 4;
        int j = (int)(f % NNODE);
        float4 w0 = *(const float4*)&g_nzT[0][j];
        float4 w1 = *(const float4*)&g_nzT[1][j];
        float4 w2 = *(const float4*)&g_nzT[2][j];
        float4 a0 = *(const float4*)&A0[f];
        float4 a1 = *(const float4*)&A1[f];
        float4 a2 = *(const float4*)&A2[f];
        float4 o;
        o.x = fmaf(w0.x, a0.x, fmaf(w1.x, a1.x, w2.x * a2.x));
        o.y = fmaf(w0.y, a0.y, fmaf(w1.y, a1.y, w2.y * a2.y));
        o.z = fmaf(w0.z, a0.z, fmaf(w1.z, a1.z, w2.z * a2.z));
        o.w = fmaf(w0.w, a0.w, fmaf(w1.w, a1.w, w2.w * a2.w));
        *(float4*)&g_adj[f] = o;
    }
}

// ---------------- tiled fp32 GEMM: C = op(A[MxK] @ B[KxN] (+bias) (relu)) ----------------
template<bool BIAS, bool RELU>
__global__ __launch_bounds__(256)
void k_gemm_nn(const float* __restrict__ A, const float* __restrict__ B,
               const float* __restrict__ bias, float* __restrict__ C,
               int M, int N, int K)
{
    __shared__ float As[16][68];
    __shared__ float Bs[16][64];
    int tid = threadIdx.x;
    int tx = tid & 15, ty = tid >> 4;
    int row0 = blockIdx.y * 64, col0 = blockIdx.x * 64;
    float acc[4][4] = {};

    int la_m = tid >> 2, la_k = (tid & 3) * 4;
    int lb_k = tid >> 4, lb_n = (tid & 15) * 4;
    const float* Aptr = A + (size_t)(row0 + la_m) * K + la_k;
    const float* Bptr = B + (size_t)lb_k * N + col0 + lb_n;

    for (int kt = 0; kt < K; kt += 16) {
        float4 va = *(const float4*)(Aptr + kt);
        float4 vb = *(const float4*)(Bptr + (size_t)kt * N);
        __syncthreads();
        As[la_k + 0][la_m] = va.x; As[la_k + 1][la_m] = va.y;
        As[la_k + 2][la_m] = va.z; As[la_k + 3][la_m] = va.w;
        *(float4*)&Bs[lb_k][lb_n] = vb;
        __syncthreads();
#pragma unroll
        for (int kk = 0; kk < 16; kk++) {
            float a[4];
            float4 bv = *(const float4*)&Bs[kk][tx * 4];
            float b[4] = { bv.x, bv.y, bv.z, bv.w };
#pragma unroll
            for (int i = 0; i < 4; i++) a[i] = As[kk][ty * 4 + i];
#pragma unroll
            for (int i = 0; i < 4; i++)
#pragma unroll
                for (int jj = 0; jj < 4; jj++)
                    acc[i][jj] = fmaf(a[i], b[jj], acc[i][jj]);
        }
    }
#pragma unroll
    for (int i = 0; i < 4; i++) {
        int r = row0 + ty * 4 + i;
#pragma unroll
        for (int jj = 0; jj < 4; jj++) {
            int cI = col0 + tx * 4 + jj;
            float v = acc[i][jj];
            if (BIAS) v += bias[cI];
            if (RELU) v = fmaxf(v, 0.f);
            C[(size_t)r * N + cI] = v;
        }
    }
}

// ---------------- NT GEMM with adjacency-mask epilogue: S = (Q @ Kh^T) * adj ----------------
__global__ __launch_bounds__(256)
void k_gemm_nt_mask(const float* __restrict__ A, const float* __restrict__ B,
                    const float* __restrict__ mask, float* __restrict__ C,
                    int M, int N, int K)
{
    __shared__ float As[16][68];
    __shared__ float Bs[16][68];
    int tid = threadIdx.x;
    int tx = tid & 15, ty = tid >> 4;
    int row0 = blockIdx.y * 64, col0 = blockIdx.x * 64;
    float acc[4][4] = {};

    int lm = tid >> 2, lk = (tid & 3) * 4;
    const float* Aptr = A + (size_t)(row0 + lm) * K + lk;
    const float* Bptr = B + (size_t)(col0 + lm) * K + lk;

    for (int kt = 0; kt < K; kt += 16) {
        float4 va = *(const float4*)(Aptr + kt);
        float4 vb = *(const float4*)(Bptr + kt);
        __syncthreads();
        As[lk + 0][lm] = va.x; As[lk + 1][lm] = va.y;
        As[lk + 2][lm] = va.z; As[lk + 3][lm] = va.w;
        Bs[lk + 0][lm] = vb.x; Bs[lk + 1][lm] = vb.y;
        Bs[lk + 2][lm] = vb.z; Bs[lk + 3][lm] = vb.w;
        __syncthreads();
#pragma unroll
        for (int kk = 0; kk < 16; kk++) {
            float a[4], b[4];
#pragma unroll
            for (int i = 0; i < 4; i++) a[i] = As[kk][ty * 4 + i];
#pragma unroll
            for (int jj = 0; jj < 4; jj++) b[jj] = Bs[kk][tx * 4 + jj];
#pragma unroll
            for (int i = 0; i < 4; i++)
#pragma unroll
                for (int jj = 0; jj < 4; jj++)
                    acc[i][jj] = fmaf(a[i], b[jj], acc[i][jj]);
        }
    }
#pragma unroll
    for (int i = 0; i < 4; i++) {
        int r = row0 + ty * 4 + i;
#pragma unroll
        for (int jj = 0; jj < 4; jj++) {
            int cI = col0 + tx * 4 + jj;
            size_t idx = (size_t)r * N + cI;
            C[idx] = acc[i][jj] * mask[idx];
        }
    }
}

// ---------------- row softmax over S (in place), one row per block ----------------
__global__ __launch_bounds__(256)
void k_softmax_rows(float* __restrict__ S)
{
    __shared__ float buf[NNODE];     // 24 KB row buffer
    __shared__ float red[8];
    __shared__ float s_bcast;
    int i = blockIdx.x, tid = threadIdx.x;
    int warp = tid >> 5, lane = tid & 31;
    float* row = S + (size_t)i * NNODE;

    float m = -INFINITY;
    for (int jv = tid; jv < NN4; jv += 256) {
        float4 v = *(const float4*)&row[jv * 4];
        *(float4*)&buf[jv * 4] = v;
        m = fmaxf(m, fmaxf(fmaxf(v.x, v.y), fmaxf(v.z, v.w)));
    }
#pragma unroll
    for (int off = 16; off; off >>= 1) m = fmaxf(m, __shfl_xor_sync(0xffffffffu, m, off));
    if (lane == 0) red[warp] = m;
    __syncthreads();
    if (tid == 0) {
        float mm = red[0];
        for (int w = 1; w < 8; w++) mm = fmaxf(mm, red[w]);
        s_bcast = mm;
    }
    __syncthreads();
    m = s_bcast;

    float sum = 0.f;
    for (int jv = tid; jv < NN4; jv += 256) {
        float4 v = *(const float4*)&buf[jv * 4];
        v.x = expf(v.x - m); v.y = expf(v.y - m);
        v.z = expf(v.z - m); v.w = expf(v.w - m);
        *(float4*)&buf[jv * 4] = v;
        sum += v.x + v.y + v.z + v.w;
    }
#pragma unroll
    for (int off = 16; off; off >>= 1) sum += __shfl_xor_sync(0xffffffffu, sum, off);
    __syncthreads();
    if (lane == 0) red[warp] = sum;
    __syncthreads();
    if (tid == 0) {
        float ss = 0.f;
        for (int w = 0; w < 8; w++) ss += red[w];
        s_bcast = 1.f / ss;
    }
    __syncthreads();
    float inv = s_bcast;
    for (int jv = tid; jv < NN4; jv += 256) {
        float4 v = *(const float4*)&buf[jv * 4];
        v.x *= inv; v.y *= inv; v.z *= inv; v.w *= inv;
        *(float4*)&row[jv * 4] = v;
    }
}

// ---------------- Y2T[c][j] = (X_tilde @ W2)[j,c] ----------------
__global__ void k_y2(const float* __restrict__ Xt, const float* __restrict__ W2)
{
    int j = blockIdx.x * blockDim.x + threadIdx.x;
    if (j >= NNODE) return;
    float acc[NC] = {};
    for (int k = 0; k < NH; k++) {
        float x = Xt[(size_t)j * NH + k];
#pragma unroll
        for (int c = 0; c < NC; c++) acc[c] = fmaf(x, __ldg(&W2[k * NC + c]), acc[c]);
    }
#pragma unroll
    for (int c = 0; c < NC; c++) g_Y2T[c][j] = acc[c];
}

// ---------------- gcn2 + final class softmax: out = softmax(adj @ Y2 + b2) ----------------
__global__ __launch_bounds__(256)
void k_gcn2(const float* __restrict__ b2, float* __restrict__ out)
{
    const int R = 8;
    int i0 = blockIdx.x * R;
    int tid = threadIdx.x;
    float acc[R][NC] = {};

    for (int jv = tid; jv < NN4; jv += 256) {
        int j = jv * 4;
        float4 y[NC];
#pragma unroll
        for (int c = 0; c < NC; c++) y[c] = *(const float4*)&g_Y2T[c][j];
#pragma unroll
        for (int r = 0; r < R; r++) {
            float4 a = *(const float4*)&g_adj[(size_t)(i0 + r) * NNODE + j];
#pragma unroll
            for (int c = 0; c < NC; c++) {
                float s = acc[r][c];
                s = fmaf(a.x, y[c].x, s); s = fmaf(a.y, y[c].y, s);
                s = fmaf(a.z, y[c].z, s); s = fmaf(a.w, y[c].w, s);
                acc[r][c] = s;
            }
        }
    }
#pragma unroll
    for (int off = 16; off; off >>= 1)
#pragma unroll
        for (int r = 0; r < R; r++)
#pragma unroll
            for (int c = 0; c < NC; c++)
                acc[r][c] += __shfl_down_sync(0xffffffffu, acc[r][c], off);

    __shared__ float red[8][64];
    __shared__ float zz[8][NC];
    int warp = tid >> 5, lane = tid & 31;
    if (lane == 0)
        for (int r = 0; r < R; r++)
            for (int c = 0; c < NC; c++)
                red[warp][r * NC + c] = acc[r][c];
    __syncthreads();
    if (tid < 64) {
        float s = 0.f;
        for (int w = 0; w < 8; w++) s += red[w][tid];
        zz[tid / NC][tid % NC] = s + b2[tid % NC];
    }
    __syncthreads();
    if (tid < 8) {
        int r = tid;
        float mx = zz[r][0];
#pragma unroll
        for (int c = 1; c < NC; c++) mx = fmaxf(mx, zz[r][c]);
        float e[NC]; float sum = 0.f;
#pragma unroll
        for (int c = 0; c < NC; c++) { e[c] = expf(zz[r][c] - mx); sum += e[c]; }
        float inv = 1.f / sum;
#pragma unroll
        for (int c = 0; c < NC; c++) out[(size_t)(i0 + r) * NC + c] = e[c] * inv;
    }
}

// ---------------- launcher ----------------
extern "C" void kernel_launch(void* const* d_in, const int* in_sizes, int n_in,
                              void* d_out, int out_size)
{
    const float* adj0 = (const float*)d_in[0];
    const float* adj1 = (const float*)d_in[1];
    const float* adj2 = (const float*)d_in[2];
    const float* features = (const float*)d_in[3];
    const float* Wa1 = (const float*)d_in[4];  const float* ba1 = (const float*)d_in[5];
    const float* Wa2 = (const float*)d_in[6];  const float* ba2 = (const float*)d_in[7];
    const float* Wa3 = (const float*)d_in[8];  const float* ba3 = (const float*)d_in[9];
    const float* Wagg = (const float*)d_in[10]; const float* bagg = (const float*)d_in[11];
    const float* W1 = (const float*)d_in[12];  const float* b1 = (const float*)d_in[13];
    const float* Wq = (const float*)d_in[14];  const float* bq = (const float*)d_in[15];
    const float* Wk = (const float*)d_in[16];  const float* bk = (const float*)d_in[17];
    const float* Wv = (const float*)d_in[18];  const float* bv = (const float*)d_in[19];
    const float* W2 = (const float*)d_in[20];  const float* b2 = (const float*)d_in[21];
    float* out = (float*)d_out;

    void *pAdj, *pS, *pH0, *px, *pQ, *pK, *pV, *pXt, *pNzScratch;
    cudaGetSymbolAddress(&pAdj, g_adj);
    cudaGetSymbolAddress(&pS, g_S);
    cudaGetSymbolAddress(&pH0, g_H0);
    cudaGetSymbolAddress(&px, g_x);
    cudaGetSymbolAddress(&pQ, g_Q);
    cudaGetSymbolAddress(&pK, g_K);
    cudaGetSymbolAddress(&pV, g_V);
    cudaGetSymbolAddress(&pXt, g_Xt);
    cudaGetSymbolAddress(&pNzScratch, g_nz_scratch);

    // output layout: [softmax(z) : N*NC][nz : N*3]
    float* nz_out = (out_size >= NNODE * (NC + 3)) ? (out + NNODE * NC)
                                                   : (float*)pNzScratch;

    k_precompute_M<<<(3 * NNODE + 255) / 256, 256>>>(Wa1, Wa2, Wa3, Wagg, ba1, ba2, ba3, bagg);
    k_z4<<<NNODE / 8, 256>>>(adj0, adj1, adj2, nz_out);
    k_combine<<<4096, 256>>>(adj0, adj1, adj2);

    // H0 = features @ W1
    k_gemm_nn<false, false><<<dim3(NH / 64, NNODE / 64), 256>>>(
        features, W1, nullptr, (float*)pH0, NNODE, NH, KFEAT);
    // x = relu(adj @ H0 + b1)
    k_gemm_nn<true, true><<<dim3(NH / 64, NNODE / 64), 256>>>(
        (const float*)pAdj, (const float*)pH0, b1, (float*)px, NNODE, NH, NNODE);
    // Q, K, V
    k_gemm_nn<true, false><<<dim3(NH / 64, NNODE / 64), 256>>>(
        (const float*)px, Wq, bq, (float*)pQ, NNODE, NH, NH);
    k_gemm_nn<true, false><<<dim3(NH / 64, NNODE / 64), 256>>>(
        (const float*)px, Wk, bk, (float*)pK, NNODE, NH, NH);
    k_gemm_nn<true, false><<<dim3(NH / 64, NNODE / 64), 256>>>(
        (const float*)px, Wv, bv, (float*)pV, NNODE, NH, NH);
    // S = (Q @ K^T) * adj
    k_gemm_nt_mask<<<dim3(NNODE / 64, NNODE / 64), 256>>>(
        (const float*)pQ, (const float*)pK, (const float*)pAdj, (float*)pS,
        NNODE, NNODE, NH);
    // attention = softmax(S) rows; gcn_norm is identity (rows sum to 1) -> skipped
    k_softmax_rows<<<NNODE, 256>>>((float*)pS);
    // X_tilde = relu(attention @ V)
    k_gemm_nn<false, true><<<dim3(NH / 64, NNODE / 64), 256>>>(
        (const float*)pS, (const float*)pV, nullptr, (float*)pXt, NNODE, NH, NNODE);
    // Y2 = X_tilde @ W2 (stored transposed)
    k_y2<<<(NNODE + 255) / 256, 256>>>((const float*)pXt, W2);
    // out = softmax(adj @ Y2 + b2)
    k_gcn2<<<NNODE / 8, 256>>>(b2, out);
}

// round 5
// speedup vs baseline: 1.4559x; 1.4559x over previous
#include <cuda_runtime.h>
#include <math.h>

#define NNODE 6144
#define KFEAT 512
#define NH 256
#define NC 8
#define AD 128
#define NN4 (NNODE/4)

typedef unsigned long long ull;

// ---------------- device scratch (no allocation allowed) ----------------
__device__ float g_adj[(size_t)NNODE * NNODE];   // combined adjacency
__device__ float g_S  [(size_t)NNODE * NNODE];   // masked logits / attention
__device__ float g_H0 [NNODE * NH];
__device__ float g_x  [NNODE * NH];
__device__ float g_Q  [NNODE * NH];
__device__ float g_K  [NNODE * NH];
__device__ float g_V  [NNODE * NH];
__device__ float g_Xt [NNODE * NH];
__device__ float g_part[3][(size_t)NNODE * NH];  // split-K partials
__device__ float g_MT [3][3][NNODE];             // folded Wa_k @ Wagg_k, transposed
__device__ float g_b4 [3];
__device__ float g_nzT[3][NNODE];                // nz transposed for coalesced combine
__device__ float g_nz_scratch[NNODE * 3];
__device__ float g_Y2T[NC][NNODE];               // (X_tilde @ W2) transposed

// ---------------- f32x2 helpers ----------------
__device__ __forceinline__ ull dup2(float a) {
    ull r; asm("mov.b64 %0, {%1, %1};" : "=l"(r) : "f"(a)); return r;
}
__device__ __forceinline__ ull pack2(float lo, float hi) {
    ull r; asm("mov.b64 %0, {%1, %2};" : "=l"(r) : "f"(lo), "f"(hi)); return r;
}
__device__ __forceinline__ void ffma2(ull& d, ull a, ull b) {
    asm("fma.rn.f32x2 %0, %1, %2, %0;" : "+l"(d) : "l"(a), "l"(b));
}
__device__ __forceinline__ float2 unpack2(ull v) {
    float2 f; asm("mov.b64 {%0, %1}, %2;" : "=f"(f.x), "=f"(f.y) : "l"(v)); return f;
}

// ---------------- fold Wa_k @ Wagg_k -> M_k [N,3], and bias b4 ----------------
__global__ void k_precompute_M(const float* __restrict__ Wa1, const float* __restrict__ Wa2,
                               const float* __restrict__ Wa3, const float* __restrict__ Wagg,
                               const float* __restrict__ ba1, const float* __restrict__ ba2,
                               const float* __restrict__ ba3, const float* __restrict__ bagg)
{
    int t = blockIdx.x * blockDim.x + threadIdx.x;
    if (t < 3 * NNODE) {
        int k = t / NNODE, j = t % NNODE;
        const float* Wa = (k == 0) ? Wa1 : ((k == 1) ? Wa2 : Wa3);
        float a0 = 0.f, a1 = 0.f, a2 = 0.f;
        for (int a = 0; a < AD; a++) {
            float w = Wa[j * AD + a];
            const float* wg = Wagg + (k * AD + a) * 3;
            a0 = fmaf(w, wg[0], a0);
            a1 = fmaf(w, wg[1], a1);
            a2 = fmaf(w, wg[2], a2);
        }
        g_MT[k][0][j] = a0; g_MT[k][1][j] = a1; g_MT[k][2][j] = a2;
    }
    if (blockIdx.x == 0 && threadIdx.x < 3) {
        int c = threadIdx.x;
        float b = bagg[c];
        for (int k = 0; k < 3; k++) {
            const float* ba = (k == 0) ? ba1 : ((k == 1) ? ba2 : ba3);
            for (int a = 0; a < AD; a++) b = fmaf(ba[a], Wagg[(k * AD + a) * 3 + c], b);
        }
        g_b4[c] = b;
    }
}

// ---------------- pass A: z4 = sum_k adj_k @ M_k + b4 ; nz = softmax(z4) ----------------
__global__ __launch_bounds__(256)
void k_z4(const float* __restrict__ A0, const float* __restrict__ A1,
          const float* __restrict__ A2, float* __restrict__ nz_out)
{
    const int R = 8;
    int i0 = blockIdx.x * R;
    int tid = threadIdx.x;
    float acc[R][3];
#pragma unroll
    for (int r = 0; r < R; r++) { acc[r][0] = 0.f; acc[r][1] = 0.f; acc[r][2] = 0.f; }

    for (int jv = tid; jv < NN4; jv += 256) {
        int j = jv * 4;
        float4 m[3][3];
#pragma unroll
        for (int k = 0; k < 3; k++)
#pragma unroll
            for (int c = 0; c < 3; c++)
                m[k][c] = *(const float4*)&g_MT[k][c][j];
#pragma unroll
        for (int r = 0; r < R; r++) {
            size_t base = (size_t)(i0 + r) * NNODE + j;
            float4 a0 = *(const float4*)&A0[base];
            float4 a1 = *(const float4*)&A1[base];
            float4 a2 = *(const float4*)&A2[base];
#pragma unroll
            for (int c = 0; c < 3; c++) {
                float s = acc[r][c];
                s = fmaf(a0.x, m[0][c].x, s); s = fmaf(a0.y, m[0][c].y, s);
                s = fmaf(a0.z, m[0][c].z, s); s = fmaf(a0.w, m[0][c].w, s);
                s = fmaf(a1.x, m[1][c].x, s); s = fmaf(a1.y, m[1][c].y, s);
                s = fmaf(a1.z, m[1][c].z, s); s = fmaf(a1.w, m[1][c].w, s);
                s = fmaf(a2.x, m[2][c].x, s); s = fmaf(a2.y, m[2][c].y, s);
                s = fmaf(a2.z, m[2][c].z, s); s = fmaf(a2.w, m[2][c].w, s);
                acc[r][c] = s;
            }
        }
    }
#pragma unroll
    for (int off = 16; off; off >>= 1)
#pragma unroll
        for (int r = 0; r < R; r++)
#pragma unroll
            for (int c = 0; c < 3; c++)
                acc[r][c] += __shfl_down_sync(0xffffffffu, acc[r][c], off);

    __shared__ float red[8][24];
    __shared__ float z[8][3];
    int warp = tid >> 5, lane = tid & 31;
    if (lane == 0)
        for (int r = 0; r < R; r++)
            for (int c = 0; c < 3; c++)
                red[warp][r * 3 + c] = acc[r][c];
    __syncthreads();
    if (tid < 24) {
        float s = 0.f;
        for (int w = 0; w < 8; w++) s += red[w][tid];
        z[tid / 3][tid % 3] = s + g_b4[tid % 3];
    }
    __syncthreads();
    if (tid < 8) {
        int r = tid;
        float a = z[r][0], b = z[r][1], c = z[r][2];
        float mx = fmaxf(a, fmaxf(b, c));
        float e0 = expf(a - mx), e1 = expf(b - mx), e2 = expf(c - mx);
        float inv = 1.f / (e0 + e1 + e2);
        e0 *= inv; e1 *= inv; e2 *= inv;
        int i = i0 + r;
        nz_out[i * 3 + 0] = e0; nz_out[i * 3 + 1] = e1; nz_out[i * 3 + 2] = e2;
        g_nzT[0][i] = e0; g_nzT[1][i] = e1; g_nzT[2][i] = e2;
    }
}

// ---------------- pass B: adj[i,j] = sum_k nz[j,k] * adj_k[i,j] ----------------
__global__ __launch_bounds__(256)
void k_combine(const float* __restrict__ A0, const float* __restrict__ A1,
               const float* __restrict__ A2)
{
    size_t total4 = (size_t)NNODE * NNODE / 4;
    size_t stride = (size_t)gridDim.x * blockDim.x;
    for (size_t idx = (size_t)blockIdx.x * blockDim.x + threadIdx.x; idx < total4; idx += stride) {
        size_t f = idx * 4;
        int j = (int)(f % NNODE);
        float4 w0 = *(const float4*)&g_nzT[0][j];
        float4 w1 = *(const float4*)&g_nzT[1][j];
        float4 w2 = *(const float4*)&g_nzT[2][j];
        float4 a0 = *(const float4*)&A0[f];
        float4 a1 = *(const float4*)&A1[f];
        float4 a2 = *(const float4*)&A2[f];
        float4 o;
        o.x = fmaf(w0.x, a0.x, fmaf(w1.x, a1.x, w2.x * a2.x));
        o.y = fmaf(w0.y, a0.y, fmaf(w1.y, a1.y, w2.y * a2.y));
        o.z = fmaf(w0.z, a0.z, fmaf(w1.z, a1.z, w2.z * a2.z));
        o.w = fmaf(w0.w, a0.w, fmaf(w1.w, a1.w, w2.w * a2.w));
        *(float4*)&g_adj[f] = o;
    }
}

// ============================================================================
// FFMA2 GEMM: 128x128 tile, BK=16, 256 threads, 8x8 microtile (split 4+4).
// A [M,K] row-major. B: NN -> [K,N]; TRANSB -> [N,K] (C = A @ B^T).
// PARTIAL: blockIdx.z selects K-slice, writes g_part[z]. MASK: C *= mask.
// ============================================================================
template<bool TRANSB, bool PARTIAL, bool BIAS, bool RELU, bool MASK>
__device__ __forceinline__
void gemm_body(const float* __restrict__ A, const float* __restrict__ B,
               const float* __restrict__ bias, const float* __restrict__ mask,
               float* __restrict__ C, int M, int N, int K, int kPerSplit)
{
    __shared__ float As[2][16][128];
    __shared__ float Bs[2][16][128];

    const int tid = threadIdx.x;
    const int tx = tid & 15, ty = tid >> 4;
    const int row0 = blockIdx.y * 128, col0 = blockIdx.x * 128;

    int k0 = 0, kLen = K;
    if (PARTIAL) {
        k0 = blockIdx.z * kPerSplit;
        kLen = min(kPerSplit, K - k0);
    }
    const int nIter = kLen >> 4;

    // global load mapping
    const int arow = tid >> 1, ak = (tid & 1) * 8;          // A (and TRANSB B)
    const int brow = tid >> 4, bcol = (tid & 15) * 8;       // NN B
    const float* Ap = A + (size_t)(row0 + arow) * K + k0 + ak;
    const float* Bp = TRANSB ? (B + (size_t)(col0 + arow) * K + k0 + ak)
                             : (B + (size_t)(k0 + brow) * N + col0 + bcol);

    float4 va0, va1, vb0, vb1;
    // prologue: load tile 0
    va0 = *(const float4*)(Ap);     va1 = *(const float4*)(Ap + 4);
    vb0 = *(const float4*)(Bp);     vb1 = *(const float4*)(Bp + 4);
    {
        As[0][ak + 0][arow] = va0.x; As[0][ak + 1][arow] = va0.y;
        As[0][ak + 2][arow] = va0.z; As[0][ak + 3][arow] = va0.w;
        As[0][ak + 4][arow] = va1.x; As[0][ak + 5][arow] = va1.y;
        As[0][ak + 6][arow] = va1.z; As[0][ak + 7][arow] = va1.w;
        if (TRANSB) {
            Bs[0][ak + 0][arow] = vb0.x; Bs[0][ak + 1][arow] = vb0.y;
            Bs[0][ak + 2][arow] = vb0.z; Bs[0][ak + 3][arow] = vb0.w;
            Bs[0][ak + 4][arow] = vb1.x; Bs[0][ak + 5][arow] = vb1.y;
            Bs[0][ak + 6][arow] = vb1.z; Bs[0][ak + 7][arow] = vb1.w;
        } else {
            *(float4*)&Bs[0][brow][bcol]     = vb0;
            *(float4*)&Bs[0][brow][bcol + 4] = vb1;
        }
    }
    __syncthreads();

    ull acc[8][4];
#pragma unroll
    for (int i = 0; i < 8; i++)
#pragma unroll
        for (int j = 0; j < 4; j++) acc[i][j] = 0ULL;

    int cur = 0;
    for (int kt = 0; kt < nIter; kt++) {
        const bool notlast = (kt + 1 < nIter);
        if (notlast) {
            const float* Ap2 = Ap + (kt + 1) * 16;
            va0 = *(const float4*)(Ap2); va1 = *(const float4*)(Ap2 + 4);
            if (TRANSB) {
                const float* Bp2 = Bp + (kt + 1) * 16;
                vb0 = *(const float4*)(Bp2); vb1 = *(const float4*)(Bp2 + 4);
            } else {
                const float* Bp2 = Bp + (size_t)(kt + 1) * 16 * N;
                vb0 = *(const float4*)(Bp2); vb1 = *(const float4*)(Bp2 + 4);
            }
        }
#pragma unroll
        for (int kk = 0; kk < 16; kk++) {
            float4 af0 = *(const float4*)&As[cur][kk][ty * 4];
            float4 af1 = *(const float4*)&As[cur][kk][64 + ty * 4];
            float4 bf0 = *(const float4*)&Bs[cur][kk][tx * 4];
            float4 bf1 = *(const float4*)&Bs[cur][kk][64 + tx * 4];
            ull bp0 = pack2(bf0.x, bf0.y), bp1 = pack2(bf0.z, bf0.w);
            ull bp2 = pack2(bf1.x, bf1.y), bp3 = pack2(bf1.z, bf1.w);
            float av[8] = { af0.x, af0.y, af0.z, af0.w, af1.x, af1.y, af1.z, af1.w };
#pragma unroll
            for (int i = 0; i < 8; i++) {
                ull aa = dup2(av[i]);
                ffma2(acc[i][0], aa, bp0);
                ffma2(acc[i][1], aa, bp1);
                ffma2(acc[i][2], aa, bp2);
                ffma2(acc[i][3], aa, bp3);
            }
        }
        if (notlast) {
            int nxt = cur ^ 1;
            As[nxt][ak + 0][arow] = va0.x; As[nxt][ak + 1][arow] = va0.y;
            As[nxt][ak + 2][arow] = va0.z; As[nxt][ak + 3][arow] = va0.w;
            As[nxt][ak + 4][arow] = va1.x; As[nxt][ak + 5][arow] = va1.y;
            As[nxt][ak + 6][arow] = va1.z; As[nxt][ak + 7][arow] = va1.w;
            if (TRANSB) {
                Bs[nxt][ak + 0][arow] = vb0.x; Bs[nxt][ak + 1][arow] = vb0.y;
                Bs[nxt][ak + 2][arow] = vb0.z; Bs[nxt][ak + 3][arow] = vb0.w;
                Bs[nxt][ak + 4][arow] = vb1.x; Bs[nxt][ak + 5][arow] = vb1.y;
                Bs[nxt][ak + 6][arow] = vb1.z; Bs[nxt][ak + 7][arow] = vb1.w;
            } else {
                *(float4*)&Bs[nxt][brow][bcol]     = vb0;
                *(float4*)&Bs[nxt][brow][bcol + 4] = vb1;
            }
            __syncthreads();
            cur = nxt;
        }
    }

    float* Cp = C;
    if (PARTIAL) Cp += (size_t)blockIdx.z * M * N;
#pragma unroll
    for (int i = 0; i < 8; i++) {
        int r = row0 + ((i < 4) ? (ty * 4 + i) : (64 + ty * 4 + (i - 4)));
#pragma unroll
        for (int g = 0; g < 2; g++) {
            int c = col0 + g * 64 + tx * 4;
            float2 p0 = unpack2(acc[i][g * 2]);
            float2 p1 = unpack2(acc[i][g * 2 + 1]);
            float4 v = { p0.x, p0.y, p1.x, p1.y };
            if (BIAS) {
                v.x += bias[c]; v.y += bias[c + 1]; v.z += bias[c + 2]; v.w += bias[c + 3];
            }
            if (MASK) {
                float4 m = *(const float4*)&mask[(size_t)r * N + c];
                v.x *= m.x; v.y *= m.y; v.z *= m.z; v.w *= m.w;
            }
            if (RELU) {
                v.x = fmaxf(v.x, 0.f); v.y = fmaxf(v.y, 0.f);
                v.z = fmaxf(v.z, 0.f); v.w = fmaxf(v.w, 0.f);
            }
            *(float4*)&Cp[(size_t)r * N + c] = v;
        }
    }
}

template<bool TRANSB, bool PARTIAL, bool BIAS, bool RELU, bool MASK>
__global__ __launch_bounds__(256)
void k_gemm128(const float* __restrict__ A, const float* __restrict__ B,
               const float* __restrict__ bias, const float* __restrict__ mask,
               float* __restrict__ C, int M, int N, int K, int kPerSplit)
{
    gemm_body<TRANSB, PARTIAL, BIAS, RELU, MASK>(A, B, bias, mask, C, M, N, K, kPerSplit);
}

// batched QKV: blockIdx.z selects (W, b, out)
__global__ __launch_bounds__(256)
void k_gemm_qkv(const float* __restrict__ x,
                const float* __restrict__ Wq, const float* __restrict__ bq, float* __restrict__ Q,
                const float* __restrict__ Wk, const float* __restrict__ bk, float* __restrict__ Kh,
                const float* __restrict__ Wv, const float* __restrict__ bv, float* __restrict__ V)
{
    const float* B = (blockIdx.z == 0) ? Wq : ((blockIdx.z == 1) ? Wk : Wv);
    const float* b = (blockIdx.z == 0) ? bq : ((blockIdx.z == 1) ? bk : bv);
    float* C = (blockIdx.z == 0) ? Q : ((blockIdx.z == 1) ? Kh : V);
    gemm_body<false, false, true, false, false>(x, B, b, nullptr, C, NNODE, NH, NH, 0);
}

// split-K reduce: C = op(p0+p1+p2 (+bias) (relu))
template<bool BIAS, bool RELU>
__global__ __launch_bounds__(256)
void k_splitk_reduce(const float* __restrict__ bias, float* __restrict__ C, int N)
{
    size_t total4 = (size_t)NNODE * NH / 4;
    size_t idx = (size_t)blockIdx.x * blockDim.x + threadIdx.x;
    if (idx >= total4) return;
    size_t f = idx * 4;
    float4 p0 = *(const float4*)&g_part[0][f];
    float4 p1 = *(const float4*)&g_part[1][f];
    float4 p2 = *(const float4*)&g_part[2][f];
    float4 v;
    v.x = p0.x + p1.x + p2.x;
    v.y = p0.y + p1.y + p2.y;
    v.z = p0.z + p1.z + p2.z;
    v.w = p0.w + p1.w + p2.w;
    if (BIAS) {
        int c = (int)(f % N);
        float4 b = *(const float4*)&bias[c];
        v.x += b.x; v.y += b.y; v.z += b.z; v.w += b.w;
    }
    if (RELU) {
        v.x = fmaxf(v.x, 0.f); v.y = fmaxf(v.y, 0.f);
        v.z = fmaxf(v.z, 0.f); v.w = fmaxf(v.w, 0.f);
    }
    *(float4*)&C[f] = v;
}

// ---------------- row softmax over S (in place), one row per block ----------------
__global__ __launch_bounds__(256)
void k_softmax_rows(float* __restrict__ S)
{
    __shared__ float buf[NNODE];
    __shared__ float red[8];
    __shared__ float s_bcast;
    int i = blockIdx.x, tid = threadIdx.x;
    int warp = tid >> 5, lane = tid & 31;
    float* row = S + (size_t)i * NNODE;

    float m = -INFINITY;
    for (int jv = tid; jv < NN4; jv += 256) {
        float4 v = *(const float4*)&row[jv * 4];
        *(float4*)&buf[jv * 4] = v;
        m = fmaxf(m, fmaxf(fmaxf(v.x, v.y), fmaxf(v.z, v.w)));
    }
#pragma unroll
    for (int off = 16; off; off >>= 1) m = fmaxf(m, __shfl_xor_sync(0xffffffffu, m, off));
    if (lane == 0) red[warp] = m;
    __syncthreads();
    if (tid == 0) {
        float mm = red[0];
        for (int w = 1; w < 8; w++) mm = fmaxf(mm, red[w]);
        s_bcast = mm;
    }
    __syncthreads();
    m = s_bcast;

    float sum = 0.f;
    for (int jv = tid; jv < NN4; jv += 256) {
        float4 v = *(const float4*)&buf[jv * 4];
        v.x = expf(v.x - m); v.y = expf(v.y - m);
        v.z = expf(v.z - m); v.w = expf(v.w - m);
        *(float4*)&buf[jv * 4] = v;
        sum += v.x + v.y + v.z + v.w;
    }
#pragma unroll
    for (int off = 16; off; off >>= 1) sum += __shfl_xor_sync(0xffffffffu, sum, off);
    __syncthreads();
    if (lane == 0) red[warp] = sum;
    __syncthreads();
    if (tid == 0) {
        float ss = 0.f;
        for (int w = 0; w < 8; w++) ss += red[w];
        s_bcast = 1.f / ss;
    }
    __syncthreads();
    float inv = s_bcast;
    for (int jv = tid; jv < NN4; jv += 256) {
        float4 v = *(const float4*)&buf[jv * 4];
        v.x *= inv; v.y *= inv; v.z *= inv; v.w *= inv;
        *(float4*)&row[jv * 4] = v;
    }
}

// ---------------- Y2T[c][j] = (X_tilde @ W2)[j,c] ----------------
__global__ void k_y2(const float* __restrict__ Xt, const float* __restrict__ W2)
{
    int j = blockIdx.x * blockDim.x + threadIdx.x;
    if (j >= NNODE) return;
    float acc[NC] = {};
    for (int k = 0; k < NH; k++) {
        float x = Xt[(size_t)j * NH + k];
#pragma unroll
        for (int c = 0; c < NC; c++) acc[c] = fmaf(x, __ldg(&W2[k * NC + c]), acc[c]);
    }
#pragma unroll
    for (int c = 0; c < NC; c++) g_Y2T[c][j] = acc[c];
}

// ---------------- gcn2 + final class softmax ----------------
__global__ __launch_bounds__(256)
void k_gcn2(const float* __restrict__ b2, float* __restrict__ out)
{
    const int R = 8;
    int i0 = blockIdx.x * R;
    int tid = threadIdx.x;
    float acc[R][NC] = {};

    for (int jv = tid; jv < NN4; jv += 256) {
        int j = jv * 4;
        float4 y[NC];
#pragma unroll
        for (int c = 0; c < NC; c++) y[c] = *(const float4*)&g_Y2T[c][j];
#pragma unroll
        for (int r = 0; r < R; r++) {
            float4 a = *(const float4*)&g_adj[(size_t)(i0 + r) * NNODE + j];
#pragma unroll
            for (int c = 0; c < NC; c++) {
                float s = acc[r][c];
                s = fmaf(a.x, y[c].x, s); s = fmaf(a.y, y[c].y, s);
                s = fmaf(a.z, y[c].z, s); s = fmaf(a.w, y[c].w, s);
                acc[r][c] = s;
            }
        }
    }
#pragma unroll
    for (int off = 16; off; off >>= 1)
#pragma unroll
        for (int r = 0; r < R; r++)
#pragma unroll
            for (int c = 0; c < NC; c++)
                acc[r][c] += __shfl_down_sync(0xffffffffu, acc[r][c], off);

    __shared__ float red[8][64];
    __shared__ float zz[8][NC];
    int warp = tid >> 5, lane = tid & 31;
    if (lane == 0)
        for (int r = 0; r < R; r++)
            for (int c = 0; c < NC; c++)
                red[warp][r * NC + c] = acc[r][c];
    __syncthreads();
    if (tid < 64) {
        float s = 0.f;
        for (int w = 0; w < 8; w++) s += red[w][tid];
        zz[tid / NC][tid % NC] = s + b2[tid % NC];
    }
    __syncthreads();
    if (tid < 8) {
        int r = tid;
        float mx = zz[r][0];
#pragma unroll
        for (int c = 1; c < NC; c++) mx = fmaxf(mx, zz[r][c]);
        float e[NC]; float sum = 0.f;
#pragma unroll
        for (int c = 0; c < NC; c++) { e[c] = expf(zz[r][c] - mx); sum += e[c]; }
        float inv = 1.f / sum;
#pragma unroll
        for (int c = 0; c < NC; c++) out[(size_t)(i0 + r) * NC + c] = e[c] * inv;
    }
}

// ---------------- launcher ----------------
extern "C" void kernel_launch(void* const* d_in, const int* in_sizes, int n_in,
                              void* d_out, int out_size)
{
    const float* adj0 = (const float*)d_in[0];
    const float* adj1 = (const float*)d_in[1];
    const float* adj2 = (const float*)d_in[2];
    const float* features = (const float*)d_in[3];
    const float* Wa1 = (const float*)d_in[4];  const float* ba1 = (const float*)d_in[5];
    const float* Wa2 = (const float*)d_in[6];  const float* ba2 = (const float*)d_in[7];
    const float* Wa3 = (const float*)d_in[8];  const float* ba3 = (const float*)d_in[9];
    const float* Wagg = (const float*)d_in[10]; const float* bagg = (const float*)d_in[11];
    const float* W1 = (const float*)d_in[12];  const float* b1 = (const float*)d_in[13];
    const float* Wq = (const float*)d_in[14];  const float* bq = (const float*)d_in[15];
    const float* Wk = (const float*)d_in[16];  const float* bk = (const float*)d_in[17];
    const float* Wv = (const float*)d_in[18];  const float* bv = (const float*)d_in[19];
    const float* W2 = (const float*)d_in[20];  const float* b2 = (const float*)d_in[21];
    float* out = (float*)d_out;

    void *pAdj, *pS, *pH0, *px, *pQ, *pK, *pV, *pXt, *pPart, *pNzScratch;
    cudaGetSymbolAddress(&pAdj, g_adj);
    cudaGetSymbolAddress(&pS, g_S);
    cudaGetSymbolAddress(&pH0, g_H0);
    cudaGetSymbolAddress(&px, g_x);
    cudaGetSymbolAddress(&pQ, g_Q);
    cudaGetSymbolAddress(&pK, g_K);
    cudaGetSymbolAddress(&pV, g_V);
    cudaGetSymbolAddress(&pXt, g_Xt);
    cudaGetSymbolAddress(&pPart, g_part);
    cudaGetSymbolAddress(&pNzScratch, g_nz_scratch);

    float* nz_out = (out_size >= NNODE * (NC + 3)) ? (out + NNODE * NC)
                                                   : (float*)pNzScratch;

    k_precompute_M<<<(3 * NNODE + 255) / 256, 256>>>(Wa1, Wa2, Wa3, Wagg, ba1, ba2, ba3, bagg);
    k_z4<<<NNODE / 8, 256>>>(adj0, adj1, adj2, nz_out);
    k_combine<<<4096, 256>>>(adj0, adj1, adj2);

    const int RED_BLKS = (NNODE * NH / 4 + 255) / 256;

    // H0 = features @ W1  (split-K=3 over K=512: 176/176/160)
    k_gemm128<false, true, false, false, false><<<dim3(NH / 128, NNODE / 128, 3), 256>>>(
        features, W1, nullptr, nullptr, (float*)pPart, NNODE, NH, KFEAT, 176);
    k_splitk_reduce<false, false><<<RED_BLKS, 256>>>(nullptr, (float*)pH0, NH);

    // x = relu(adj @ H0 + b1)   (split-K=3 over K=6144: 2048 each)
    k_gemm128<false, true, false, false, false><<<dim3(NH / 128, NNODE / 128, 3), 256>>>(
        (const float*)pAdj, (const float*)pH0, nullptr, nullptr, (float*)pPart,
        NNODE, NH, NNODE, 2048);
    k_splitk_reduce<true, true><<<RED_BLKS, 256>>>(b1, (float*)px, NH);

    // Q, K, V (batched, grid.z = 3)
    k_gemm_qkv<<<dim3(NH / 128, NNODE / 128, 3), 256>>>(
        (const float*)px, Wq, bq, (float*)pQ, Wk, bk, (float*)pK, Wv, bv, (float*)pV);

    // S = (Q @ K^T) * adj
    k_gemm128<true, false, false, false, true><<<dim3(NNODE / 128, NNODE / 128), 256>>>(
        (const float*)pQ, (const float*)pK, nullptr, (const float*)pAdj, (float*)pS,
        NNODE, NNODE, NH, 0);

    // attention = softmax(S) rows; gcn_norm is identity -> skipped
    k_softmax_rows<<<NNODE, 256>>>((float*)pS);

    // X_tilde = relu(attention @ V)  (split-K=3)
    k_gemm128<false, true, false, false, false><<<dim3(NH / 128, NNODE / 128, 3), 256>>>(
        (const float*)pS, (const float*)pV, nullptr, nullptr, (float*)pPart,
        NNODE, NH, NNODE, 2048);
    k_splitk_reduce<false, true><<<RED_BLKS, 256>>>(nullptr, (float*)pXt, NH);

    // Y2 = X_tilde @ W2 (stored transposed)
    k_y2<<<(NNODE + 255) / 256, 256>>>((const float*)pXt, W2);
    // out = softmax(adj @ Y2 + b2)
    k_gcn2<<<NNODE / 8, 256>>>(b2, out);
}

// round 8
// speedup vs baseline: 1.4619x; 1.0041x over previous
#include <cuda_runtime.h>
#include <math.h>

#define NNODE 6144
#define KFEAT 512
#define NH 256
#define NC 8
#define AD 128
#define NN4 (NNODE/4)

typedef unsigned long long ull;

// ---------------- device scratch (no allocation allowed) ----------------
__device__ float g_adj[(size_t)NNODE * NNODE];   // combined adjacency
__device__ float g_S  [(size_t)NNODE * NNODE];   // masked logits / attention
__device__ float g_H0 [NNODE * NH];
__device__ float g_x  [NNODE * NH];
__device__ float g_Q  [NNODE * NH];
__device__ float g_K  [NNODE * NH];
__device__ float g_V  [NNODE * NH];
__device__ float g_Xt [NNODE * NH];
__device__ float g_part[3][(size_t)NNODE * NH];  // split-K partials
__device__ float g_MT [3][3][NNODE];             // folded Wa_k @ Wagg_k, transposed
__device__ float g_b4 [3];
__device__ float g_nzT[3][NNODE];                // nz transposed for coalesced combine
__device__ float g_nz_scratch[NNODE * 3];
__device__ float g_Y2T[NC][NNODE];               // (X_tilde @ W2) transposed

// ---------------- f32x2 helpers ----------------
__device__ __forceinline__ ull dup2(float a) {
    ull r; asm("mov.b64 %0, {%1, %1};" : "=l"(r) : "f"(a)); return r;
}
__device__ __forceinline__ ull pack2(float lo, float hi) {
    ull r; asm("mov.b64 %0, {%1, %2};" : "=l"(r) : "f"(lo), "f"(hi)); return r;
}
__device__ __forceinline__ void ffma2(ull& d, ull a, ull b) {
    asm("fma.rn.f32x2 %0, %1, %2, %0;" : "+l"(d) : "l"(a), "l"(b));
}
__device__ __forceinline__ float2 unpack2(ull v) {
    float2 f; asm("mov.b64 {%0, %1}, %2;" : "=f"(f.x), "=f"(f.y) : "l"(v)); return f;
}

// ---------------- fold Wa_k @ Wagg_k -> M_k [N,3], and bias b4 ----------------
__global__ void k_precompute_M(const float* __restrict__ Wa1, const float* __restrict__ Wa2,
                               const float* __restrict__ Wa3, const float* __restrict__ Wagg,
                               const float* __restrict__ ba1, const float* __restrict__ ba2,
                               const float* __restrict__ ba3, const float* __restrict__ bagg)
{
    int t = blockIdx.x * blockDim.x + threadIdx.x;
    if (t < 3 * NNODE) {
        int k = t / NNODE, j = t % NNODE;
        const float* Wa = (k == 0) ? Wa1 : ((k == 1) ? Wa2 : Wa3);
        float a0 = 0.f, a1 = 0.f, a2 = 0.f;
        for (int a = 0; a < AD; a++) {
            float w = Wa[j * AD + a];
            const float* wg = Wagg + (k * AD + a) * 3;
            a0 = fmaf(w, wg[0], a0);
            a1 = fmaf(w, wg[1], a1);
            a2 = fmaf(w, wg[2], a2);
        }
        g_MT[k][0][j] = a0; g_MT[k][1][j] = a1; g_MT[k][2][j] = a2;
    }
    if (blockIdx.x == 0 && threadIdx.x < 3) {
        int c = threadIdx.x;
        float b = bagg[c];
        for (int k = 0; k < 3; k++) {
            const float* ba = (k == 0) ? ba1 : ((k == 1) ? ba2 : ba3);
            for (int a = 0; a < AD; a++) b = fmaf(ba[a], Wagg[(k * AD + a) * 3 + c], b);
        }
        g_b4[c] = b;
    }
}

// ---------------- pass A: z4 = sum_k adj_k @ M_k + b4 ; nz = softmax(z4) ----------------
__global__ __launch_bounds__(256)
void k_z4(const float* __restrict__ A0, const float* __restrict__ A1,
          const float* __restrict__ A2, float* __restrict__ nz_out)
{
    const int R = 8;
    int i0 = blockIdx.x * R;
    int tid = threadIdx.x;
    float acc[R][3];
#pragma unroll
    for (int r = 0; r < R; r++) { acc[r][0] = 0.f; acc[r][1] = 0.f; acc[r][2] = 0.f; }

    for (int jv = tid; jv < NN4; jv += 256) {
        int j = jv * 4;
        float4 m[3][3];
#pragma unroll
        for (int k = 0; k < 3; k++)
#pragma unroll
            for (int c = 0; c < 3; c++)
                m[k][c] = *(const float4*)&g_MT[k][c][j];
#pragma unroll
        for (int r = 0; r < R; r++) {
            size_t base = (size_t)(i0 + r) * NNODE + j;
            float4 a0 = *(const float4*)&A0[base];
            float4 a1 = *(const float4*)&A1[base];
            float4 a2 = *(const float4*)&A2[base];
#pragma unroll
            for (int c = 0; c < 3; c++) {
                float s = acc[r][c];
                s = fmaf(a0.x, m[0][c].x, s); s = fmaf(a0.y, m[0][c].y, s);
                s = fmaf(a0.z, m[0][c].z, s); s = fmaf(a0.w, m[0][c].w, s);
                s = fmaf(a1.x, m[1][c].x, s); s = fmaf(a1.y, m[1][c].y, s);
                s = fmaf(a1.z, m[1][c].z, s); s = fmaf(a1.w, m[1][c].w, s);
                s = fmaf(a2.x, m[2][c].x, s); s = fmaf(a2.y, m[2][c].y, s);
                s = fmaf(a2.z, m[2][c].z, s); s = fmaf(a2.w, m[2][c].w, s);
                acc[r][c] = s;
            }
        }
    }
#pragma unroll
    for (int off = 16; off; off >>= 1)
#pragma unroll
        for (int r = 0; r < R; r++)
#pragma unroll
            for (int c = 0; c < 3; c++)
                acc[r][c] += __shfl_down_sync(0xffffffffu, acc[r][c], off);

    __shared__ float red[8][24];
    __shared__ float z[8][3];
    int warp = tid >> 5, lane = tid & 31;
    if (lane == 0)
        for (int r = 0; r < R; r++)
            for (int c = 0; c < 3; c++)
                red[warp][r * 3 + c] = acc[r][c];
    __syncthreads();
    if (tid < 24) {
        float s = 0.f;
        for (int w = 0; w < 8; w++) s += red[w][tid];
        z[tid / 3][tid % 3] = s + g_b4[tid % 3];
    }
    __syncthreads();
    if (tid < 8) {
        int r = tid;
        float a = z[r][0], b = z[r][1], c = z[r][2];
        float mx = fmaxf(a, fmaxf(b, c));
        float e0 = expf(a - mx), e1 = expf(b - mx), e2 = expf(c - mx);
        float inv = 1.f / (e0 + e1 + e2);
        e0 *= inv; e1 *= inv; e2 *= inv;
        int i = i0 + r;
        nz_out[i * 3 + 0] = e0; nz_out[i * 3 + 1] = e1; nz_out[i * 3 + 2] = e2;
        g_nzT[0][i] = e0; g_nzT[1][i] = e1; g_nzT[2][i] = e2;
    }
}

// ---------------- pass B: adj[i,j] = sum_k nz[j,k] * adj_k[i,j] ----------------
__global__ __launch_bounds__(256)
void k_combine(const float* __restrict__ A0, const float* __restrict__ A1,
               const float* __restrict__ A2)
{
    size_t total4 = (size_t)NNODE * NNODE / 4;
    size_t stride = (size_t)gridDim.x * blockDim.x;
    for (size_t idx = (size_t)blockIdx.x * blockDim.x + threadIdx.x; idx < total4; idx += stride) {
        size_t f = idx * 4;
        int j = (int)(f % NNODE);
        float4 w0 = *(const float4*)&g_nzT[0][j];
        float4 w1 = *(const float4*)&g_nzT[1][j];
        float4 w2 = *(const float4*)&g_nzT[2][j];
        float4 a0 = *(const float4*)&A0[f];
        float4 a1 = *(const float4*)&A1[f];
        float4 a2 = *(const float4*)&A2[f];
        float4 o;
        o.x = fmaf(w0.x, a0.x, fmaf(w1.x, a1.x, w2.x * a2.x));
        o.y = fmaf(w0.y, a0.y, fmaf(w1.y, a1.y, w2.y * a2.y));
        o.z = fmaf(w0.z, a0.z, fmaf(w1.z, a1.z, w2.z * a2.z));
        o.w = fmaf(w0.w, a0.w, fmaf(w1.w, a1.w, w2.w * a2.w));
        *(float4*)&g_adj[f] = o;
    }
}

// ============================================================================
// FFMA2 GEMM: 128x128 tile, BK=16, 256 threads, 8x8 microtile (split 4+4).
// A [M,K] row-major. B: NN -> [K,N]; TRANSB -> [N,K] (C = A @ B^T).
// PARTIAL: blockIdx.z selects K-slice, writes g_part[z]. MASK: C *= mask.
// ============================================================================
template<bool TRANSB, bool PARTIAL, bool BIAS, bool RELU, bool MASK>
__device__ __forceinline__
void gemm_body(const float* __restrict__ A, const float* __restrict__ B,
               const float* __restrict__ bias, const float* __restrict__ mask,
               float* __restrict__ C, int M, int N, int K, int kPerSplit)
{
    __shared__ float As[2][16][128];
    __shared__ float Bs[2][16][128];

    const int tid = threadIdx.x;
    const int tx = tid & 15, ty = tid >> 4;
    const int row0 = blockIdx.y * 128, col0 = blockIdx.x * 128;

    int k0 = 0, kLen = K;
    if (PARTIAL) {
        k0 = blockIdx.z * kPerSplit;
        kLen = min(kPerSplit, K - k0);
    }
    const int nIter = kLen >> 4;

    // global load mapping
    const int arow = tid >> 1, ak = (tid & 1) * 8;          // A (and TRANSB B)
    const int brow = tid >> 4, bcol = (tid & 15) * 8;       // NN B
    const float* Ap = A + (size_t)(row0 + arow) * K + k0 + ak;
    const float* Bp = TRANSB ? (B + (size_t)(col0 + arow) * K + k0 + ak)
                             : (B + (size_t)(k0 + brow) * N + col0 + bcol);

    float4 va0, va1, vb0, vb1;
    // prologue: load tile 0
    va0 = *(const float4*)(Ap);     va1 = *(const float4*)(Ap + 4);
    vb0 = *(const float4*)(Bp);     vb1 = *(const float4*)(Bp + 4);
    {
        As[0][ak + 0][arow] = va0.x; As[0][ak + 1][arow] = va0.y;
        As[0][ak + 2][arow] = va0.z; As[0][ak + 3][arow] = va0.w;
        As[0][ak + 4][arow] = va1.x; As[0][ak + 5][arow] = va1.y;
        As[0][ak + 6][arow] = va1.z; As[0][ak + 7][arow] = va1.w;
        if (TRANSB) {
            Bs[0][ak + 0][arow] = vb0.x; Bs[0][ak + 1][arow] = vb0.y;
            Bs[0][ak + 2][arow] = vb0.z; Bs[0][ak + 3][arow] = vb0.w;
            Bs[0][ak + 4][arow] = vb1.x; Bs[0][ak + 5][arow] = vb1.y;
            Bs[0][ak + 6][arow] = vb1.z; Bs[0][ak + 7][arow] = vb1.w;
        } else {
            *(float4*)&Bs[0][brow][bcol]     = vb0;
            *(float4*)&Bs[0][brow][bcol + 4] = vb1;
        }
    }
    __syncthreads();

    ull acc[8][4];
#pragma unroll
    for (int i = 0; i < 8; i++)
#pragma unroll
        for (int j = 0; j < 4; j++) acc[i][j] = 0ULL;

    int cur = 0;
    for (int kt = 0; kt < nIter; kt++) {
        const bool notlast = (kt + 1 < nIter);
        if (notlast) {
            const float* Ap2 = Ap + (kt + 1) * 16;
            va0 = *(const float4*)(Ap2); va1 = *(const float4*)(Ap2 + 4);
            if (TRANSB) {
                const float* Bp2 = Bp + (kt + 1) * 16;
                vb0 = *(const float4*)(Bp2); vb1 = *(const float4*)(Bp2 + 4);
            } else {
                const float* Bp2 = Bp + (size_t)(kt + 1) * 16 * N;
                vb0 = *(const float4*)(Bp2); vb1 = *(const float4*)(Bp2 + 4);
            }
        }
#pragma unroll
        for (int kk = 0; kk < 16; kk++) {
            float4 af0 = *(const float4*)&As[cur][kk][ty * 4];
            float4 af1 = *(const float4*)&As[cur][kk][64 + ty * 4];
            float4 bf0 = *(const float4*)&Bs[cur][kk][tx * 4];
            float4 bf1 = *(const float4*)&Bs[cur][kk][64 + tx * 4];
            ull bp0 = pack2(bf0.x, bf0.y), bp1 = pack2(bf0.z, bf0.w);
            ull bp2 = pack2(bf1.x, bf1.y), bp3 = pack2(bf1.z, bf1.w);
            float av[8] = { af0.x, af0.y, af0.z, af0.w, af1.x, af1.y, af1.z, af1.w };
#pragma unroll
            for (int i = 0; i < 8; i++) {
                ull aa = dup2(av[i]);
                ffma2(acc[i][0], aa, bp0);
                ffma2(acc[i][1], aa, bp1);
                ffma2(acc[i][2], aa, bp2);
                ffma2(acc[i][3], aa, bp3);
            }
        }
        if (notlast) {
            int nxt = cur ^ 1;
            As[nxt][ak + 0][arow] = va0.x; As[nxt][ak + 1][arow] = va0.y;
            As[nxt][ak + 2][arow] = va0.z; As[nxt][ak + 3][arow] = va0.w;
            As[nxt][ak + 4][arow] = va1.x; As[nxt][ak + 5][arow] = va1.y;
            As[nxt][ak + 6][arow] = va1.z; As[nxt][ak + 7][arow] = va1.w;
            if (TRANSB) {
                Bs[nxt][ak + 0][arow] = vb0.x; Bs[nxt][ak + 1][arow] = vb0.y;
                Bs[nxt][ak + 2][arow] = vb0.z; Bs[nxt][ak + 3][arow] = vb0.w;
                Bs[nxt][ak + 4][arow] = vb1.x; Bs[nxt][ak + 5][arow] = vb1.y;
                Bs[nxt][ak + 6][arow] = vb1.z; Bs[nxt][ak + 7][arow] = vb1.w;
            } else {
                *(float4*)&Bs[nxt][brow][bcol]     = vb0;
                *(float4*)&Bs[nxt][brow][bcol + 4] = vb1;
            }
            __syncthreads();
            cur = nxt;
        }
    }

    float* Cp = C;
    if (PARTIAL) Cp += (size_t)blockIdx.z * M * N;
#pragma unroll
    for (int i = 0; i < 8; i++) {
        int r = row0 + ((i < 4) ? (ty * 4 + i) : (64 + ty * 4 + (i - 4)));
#pragma unroll
        for (int g = 0; g < 2; g++) {
            int c = col0 + g * 64 + tx * 4;
            float2 p0 = unpack2(acc[i][g * 2]);
            float2 p1 = unpack2(acc[i][g * 2 + 1]);
            float4 v = { p0.x, p0.y, p1.x, p1.y };
            if (BIAS) {
                v.x += bias[c]; v.y += bias[c + 1]; v.z += bias[c + 2]; v.w += bias[c + 3];
            }
            if (MASK) {
                float4 m = *(const float4*)&mask[(size_t)r * N + c];
                v.x *= m.x; v.y *= m.y; v.z *= m.z; v.w *= m.w;
            }
            if (RELU) {
                v.x = fmaxf(v.x, 0.f); v.y = fmaxf(v.y, 0.f);
                v.z = fmaxf(v.z, 0.f); v.w = fmaxf(v.w, 0.f);
            }
            *(float4*)&Cp[(size_t)r * N + c] = v;
        }
    }
}

template<bool TRANSB, bool PARTIAL, bool BIAS, bool RELU, bool MASK>
__global__ __launch_bounds__(256)
void k_gemm128(const float* __restrict__ A, const float* __restrict__ B,
               const float* __restrict__ bias, const float* __restrict__ mask,
               float* __restrict__ C, int M, int N, int K, int kPerSplit)
{
    gemm_body<TRANSB, PARTIAL, BIAS, RELU, MASK>(A, B, bias, mask, C, M, N, K, kPerSplit);
}

// batched QKV: blockIdx.z selects (W, b, out)
__global__ __launch_bounds__(256)
void k_gemm_qkv(const float* __restrict__ x,
                const float* __restrict__ Wq, const float* __restrict__ bq, float* __restrict__ Q,
                const float* __restrict__ Wk, const float* __restrict__ bk, float* __restrict__ Kh,
                const float* __restrict__ Wv, const float* __restrict__ bv, float* __restrict__ V)
{
    const float* B = (blockIdx.z == 0) ? Wq : ((blockIdx.z == 1) ? Wk : Wv);
    const float* b = (blockIdx.z == 0) ? bq : ((blockIdx.z == 1) ? bk : bv);
    float* C = (blockIdx.z == 0) ? Q : ((blockIdx.z == 1) ? Kh : V);
    gemm_body<false, false, true, false, false>(x, B, b, nullptr, C, NNODE, NH, NH, 0);
}

// split-K reduce: C = op(p0+p1+p2 (+bias) (relu))
template<bool BIAS, bool RELU>
__global__ __launch_bounds__(256)
void k_splitk_reduce(const float* __restrict__ bias, float* __restrict__ C, int N)
{
    size_t total4 = (size_t)NNODE * NH / 4;
    size_t idx = (size_t)blockIdx.x * blockDim.x + threadIdx.x;
    if (idx >= total4) return;
    size_t f = idx * 4;
    float4 p0 = *(const float4*)&g_part[0][f];
    float4 p1 = *(const float4*)&g_part[1][f];
    float4 p2 = *(const float4*)&g_part[2][f];
    float4 v;
    v.x = p0.x + p1.x + p2.x;
    v.y = p0.y + p1.y + p2.y;
    v.z = p0.z + p1.z + p2.z;
    v.w = p0.w + p1.w + p2.w;
    if (BIAS) {
        int c = (int)(f % N);
        float4 b = *(const float4*)&bias[c];
        v.x += b.x; v.y += b.y; v.z += b.z; v.w += b.w;
    }
    if (RELU) {
        v.x = fmaxf(v.x, 0.f); v.y = fmaxf(v.y, 0.f);
        v.z = fmaxf(v.z, 0.f); v.w = fmaxf(v.w, 0.f);
    }
    *(float4*)&C[f] = v;
}

// ---------------- row softmax over S (in place), one row per block ----------------
__global__ __launch_bounds__(256)
void k_softmax_rows(float* __restrict__ S)
{
    __shared__ float buf[NNODE];
    __shared__ float red[8];
    __shared__ float s_bcast;
    int i = blockIdx.x, tid = threadIdx.x;
    int warp = tid >> 5, lane = tid & 31;
    float* row = S + (size_t)i * NNODE;

    float m = -INFINITY;
    for (int jv = tid; jv < NN4; jv += 256) {
        float4 v = *(const float4*)&row[jv * 4];
        *(float4*)&buf[jv * 4] = v;
        m = fmaxf(m, fmaxf(fmaxf(v.x, v.y), fmaxf(v.z, v.w)));
    }
#pragma unroll
    for (int off = 16; off; off >>= 1) m = fmaxf(m, __shfl_xor_sync(0xffffffffu, m, off));
    if (lane == 0) red[warp] = m;
    __syncthreads();
    if (tid == 0) {
        float mm = red[0];
        for (int w = 1; w < 8; w++) mm = fmaxf(mm, red[w]);
        s_bcast = mm;
    }
    __syncthreads();
    m = s_bcast;

    float sum = 0.f;
    for (int jv = tid; jv < NN4; jv += 256) {
        float4 v = *(const float4*)&buf[jv * 4];
        v.x = expf(v.x - m); v.y = expf(v.y - m);
        v.z = expf(v.z - m); v.w = expf(v.w - m);
        *(float4*)&buf[jv * 4] = v;
        sum += v.x + v.y + v.z + v.w;
    }
#pragma unroll
    for (int off = 16; off; off >>= 1) sum += __shfl_xor_sync(0xffffffffu, sum, off);
    __syncthreads();
    if (lane == 0) red[warp] = sum;
    __syncthreads();
    if (tid == 0) {
        float ss = 0.f;
        for (int w = 0; w < 8; w++) ss += red[w];
        s_bcast = 1.f / ss;
    }
    __syncthreads();
    float inv = s_bcast;
    for (int jv = tid; jv < NN4; jv += 256) {
        float4 v = *(const float4*)&buf[jv * 4];
        v.x *= inv; v.y *= inv; v.z *= inv; v.w *= inv;
        *(float4*)&row[jv * 4] = v;
    }
}

// ---------------- Y2T[c][j] = (X_tilde @ W2)[j,c] ----------------
__global__ void k_y2(const float* __restrict__ Xt, const float* __restrict__ W2)
{
    int j = blockIdx.x * blockDim.x + threadIdx.x;
    if (j >= NNODE) return;
    float acc[NC] = {};
    for (int k = 0; k < NH; k++) {
        float x = Xt[(size_t)j * NH + k];
#pragma unroll
        for (int c = 0; c < NC; c++) acc[c] = fmaf(x, __ldg(&W2[k * NC + c]), acc[c]);
    }
#pragma unroll
    for (int c = 0; c < NC; c++) g_Y2T[c][j] = acc[c];
}

// ---------------- gcn2 + final class softmax ----------------
__global__ __launch_bounds__(256)
void k_gcn2(const float* __restrict__ b2, float* __restrict__ out)
{
    const int R = 8;
    int i0 = blockIdx.x * R;
    int tid = threadIdx.x;
    float acc[R][NC] = {};

    for (int jv = tid; jv < NN4; jv += 256) {
        int j = jv * 4;
        float4 y[NC];
#pragma unroll
        for (int c = 0; c < NC; c++) y[c] = *(const float4*)&g_Y2T[c][j];
#pragma unroll
        for (int r = 0; r < R; r++) {
            float4 a = *(const float4*)&g_adj[(size_t)(i0 + r) * NNODE + j];
#pragma unroll
            for (int c = 0; c < NC; c++) {
                float s = acc[r][c];
                s = fmaf(a.x, y[c].x, s); s = fmaf(a.y, y[c].y, s);
                s = fmaf(a.z, y[c].z, s); s = fmaf(a.w, y[c].w, s);
                acc[r][c] = s;
            }
        }
    }
#pragma unroll
    for (int off = 16; off; off >>= 1)
#pragma unroll
        for (int r = 0; r < R; r++)
#pragma unroll
            for (int c = 0; c < NC; c++)
                acc[r][c] += __shfl_down_sync(0xffffffffu, acc[r][c], off);

    __shared__ float red[8][64];
    __shared__ float zz[8][NC];
    int warp = tid >> 5, lane = tid & 31;
    if (lane == 0)
        for (int r = 0; r < R; r++)
            for (int c = 0; c < NC; c++)
                red[warp][r * NC + c] = acc[r][c];
    __syncthreads();
    if (tid < 64) {
        float s = 0.f;
        for (int w = 0; w < 8; w++) s += red[w][tid];
        zz[tid / NC][tid % NC] = s + b2[tid % NC];
    }
    __syncthreads();
    if (tid < 8) {
        int r = tid;
        float mx = zz[r][0];
#pragma unroll
        for (int c = 1; c < NC; c++) mx = fmaxf(mx, zz[r][c]);
        float e[NC]; float sum = 0.f;
#pragma unroll
        for (int c = 0; c < NC; c++) { e[c] = expf(zz[r][c] - mx); sum += e[c]; }
        float inv = 1.f / sum;
#pragma unroll
        for (int c = 0; c < NC; c++) out[(size_t)(i0 + r) * NC + c] = e[c] * inv;
    }
}

// ---------------- launcher ----------------
extern "C" void kernel_launch(void* const* d_in, const int* in_sizes, int n_in,
                              void* d_out, int out_size)
{
    const float* adj0 = (const float*)d_in[0];
    const float* adj1 = (const float*)d_in[1];
    const float* adj2 = (const float*)d_in[2];
    const float* features = (const float*)d_in[3];
    const float* Wa1 = (const float*)d_in[4];  const float* ba1 = (const float*)d_in[5];
    const float* Wa2 = (const float*)d_in[6];  const float* ba2 = (const float*)d_in[7];
    const float* Wa3 = (const float*)d_in[8];  const float* ba3 = (const float*)d_in[9];
    const float* Wagg = (const float*)d_in[10]; const float* bagg = (const float*)d_in[11];
    const float* W1 = (const float*)d_in[12];  const float* b1 = (const float*)d_in[13];
    const float* Wq = (const float*)d_in[14];  const float* bq = (const float*)d_in[15];
    const float* Wk = (const float*)d_in[16];  const float* bk = (const float*)d_in[17];
    const float* Wv = (const float*)d_in[18];  const float* bv = (const float*)d_in[19];
    const float* W2 = (const float*)d_in[20];  const float* b2 = (const float*)d_in[21];
    float* out = (float*)d_out;

    void *pAdj, *pS, *pH0, *px, *pQ, *pK, *pV, *pXt, *pPart, *pNzScratch;
    cudaGetSymbolAddress(&pAdj, g_adj);
    cudaGetSymbolAddress(&pS, g_S);
    cudaGetSymbolAddress(&pH0, g_H0);
    cudaGetSymbolAddress(&px, g_x);
    cudaGetSymbolAddress(&pQ, g_Q);
    cudaGetSymbolAddress(&pK, g_K);
    cudaGetSymbolAddress(&pV, g_V);
    cudaGetSymbolAddress(&pXt, g_Xt);
    cudaGetSymbolAddress(&pPart, g_part);
    cudaGetSymbolAddress(&pNzScratch, g_nz_scratch);

    float* nz_out = (out_size >= NNODE * (NC + 3)) ? (out + NNODE * NC)
                                                   : (float*)pNzScratch;

    k_precompute_M<<<(3 * NNODE + 255) / 256, 256>>>(Wa1, Wa2, Wa3, Wagg, ba1, ba2, ba3, bagg);
    k_z4<<<NNODE / 8, 256>>>(adj0, adj1, adj2, nz_out);
    k_combine<<<4096, 256>>>(adj0, adj1, adj2);

    const int RED_BLKS = (NNODE * NH / 4 + 255) / 256;

    // H0 = features @ W1  (split-K=3 over K=512: 176/176/160)
    k_gemm128<false, true, false, false, false><<<dim3(NH / 128, NNODE / 128, 3), 256>>>(
        features, W1, nullptr, nullptr, (float*)pPart, NNODE, NH, KFEAT, 176);
    k_splitk_reduce<false, false><<<RED_BLKS, 256>>>(nullptr, (float*)pH0, NH);

    // x = relu(adj @ H0 + b1)   (split-K=3 over K=6144: 2048 each)
    k_gemm128<false, true, false, false, false><<<dim3(NH / 128, NNODE / 128, 3), 256>>>(
        (const float*)pAdj, (const float*)pH0, nullptr, nullptr, (float*)pPart,
        NNODE, NH, NNODE, 2048);
    k_splitk_reduce<true, true><<<RED_BLKS, 256>>>(b1, (float*)px, NH);

    // Q, K, V (batched, grid.z = 3)
    k_gemm_qkv<<<dim3(NH / 128, NNODE / 128, 3), 256>>>(
        (const float*)px, Wq, bq, (float*)pQ, Wk, bk, (float*)pK, Wv, bv, (float*)pV);

    // S = (Q @ K^T) * adj
    k_gemm128<true, false, false, false, true><<<dim3(NNODE / 128, NNODE / 128), 256>>>(
        (const float*)pQ, (const float*)pK, nullptr, (const float*)pAdj, (float*)pS,
        NNODE, NNODE, NH, 0);

    // attention = softmax(S) rows; gcn_norm is identity -> skipped
    k_softmax_rows<<<NNODE, 256>>>((float*)pS);

    // X_tilde = relu(attention @ V)  (split-K=3)
    k_gemm128<false, true, false, false, false><<<dim3(NH / 128, NNODE / 128, 3), 256>>>(
        (const float*)pS, (const float*)pV, nullptr, nullptr, (float*)pPart,
        NNODE, NH, NNODE, 2048);
    k_splitk_reduce<false, true><<<RED_BLKS, 256>>>(nullptr, (float*)pXt, NH);

    // Y2 = X_tilde @ W2 (stored transposed)
    k_y2<<<(NNODE + 255) / 256, 256>>>((const float*)pXt, W2);
    // out = softmax(adj @ Y2 + b2)
    k_gcn2<<<NNODE / 8, 256>>>(b2, out);
}